// round 14
// baseline (speedup 1.0000x reference)
#include <cuda_runtime.h>
#include <cuda_bf16.h>

// Mat2Twist: out[b] = theta * axis, theta = acos((tr-1)/2),
// axis = (m21-m12, m02-m20, m10-m01) / (2*sin(theta)).
// Uses sin(acos(c)) == sqrt(1-c^2), exact on theta in (0, pi).
//
// R13: R12 (3-stage cp.async ring, TILE=256, 30KB smem) with:
//   - grid = 1024: exactly ntiles/grid = 16 tiles per block (B=4194304),
//     all blocks resident (capacity 7/SM x 152 = 1064) -> no straggler wave.
//   - streaming stores (__stcs) for the write-once output stream to avoid
//     evicting read sectors from L2.

__device__ __forceinline__ float twist_factor(float tr) {
    float c = 0.5f * (tr - 1.0f);
    c = fminf(fmaxf(c, -1.0f), 1.0f);
    float ang = acosf(c);
    float s2  = fmaxf(fmaf(-c, c, 1.0f), 1e-20f);  // 1 - c^2
    return 0.5f * ang * rsqrtf(s2);                // theta / (2 sin theta)
}

constexpr int THREADS = 256;
constexpr int TILE    = 256;            // matrices per tile
constexpr int T_INF4  = TILE * 9 / 4;   // 576 float4 in per tile
constexpr int T_OUTF4 = TILE * 3 / 4;   // 192 float4 out per tile
constexpr int STAGES  = 3;

__device__ __forceinline__ void cp_async16(void* smem_ptr, const void* gptr) {
    unsigned s = (unsigned)__cvta_generic_to_shared(smem_ptr);
    asm volatile("cp.async.cg.shared.global [%0], [%1], 16;\n"
                 :: "r"(s), "l"(gptr));
}
__device__ __forceinline__ void cp_commit() {
    asm volatile("cp.async.commit_group;\n" ::: "memory");
}
template <int N>
__device__ __forceinline__ void cp_wait() {
    asm volatile("cp.async.wait_group %0;\n" :: "n"(N) : "memory");
}

__global__ __launch_bounds__(THREADS)
void mat2twist_pipe3_kernel(const float4* __restrict__ in,
                            float4* __restrict__ out, int ntiles) {
    __shared__ float sbuf[STAGES][TILE * 9];  // 3 x 9KB input ring
    __shared__ float sout[TILE * 3];          // 3KB output staging
    const int tid = threadIdx.x;

    const int t0     = blockIdx.x;
    const int stride = gridDim.x;

    // prologue: prefetch first STAGES tiles (empty groups keep FIFO exact)
#pragma unroll
    for (int p = 0; p < STAGES; ++p) {
        long long tile = (long long)t0 + (long long)p * stride;
        if (tile < ntiles) {
            const float4* gp = in + (size_t)tile * T_INF4;
            float4* sp = reinterpret_cast<float4*>(sbuf[p]);
#pragma unroll
            for (int i = tid; i < T_INF4; i += THREADS)
                cp_async16(&sp[i], &gp[i]);
        }
        cp_commit();
    }

    int buf = 0;
    for (int t = t0; t < ntiles; t += stride) {
        cp_wait<STAGES - 1>();   // oldest in-flight group (= this buf) done
        __syncthreads();

        // compute: one matrix per thread (stride-9 LDS base: conflict-free)
        const float* sb = sbuf[buf];
        {
            const float* a = sb + 9 * tid;
            float m1 = a[1], m2 = a[2], m3 = a[3];
            float m5 = a[5], m6 = a[6], m7 = a[7];
            float f  = twist_factor(a[0] + a[4] + a[8]);
            float* o = sout + 3 * tid;        // stride-3: conflict-free
            o[0] = f * (m7 - m5);             // m21 - m12
            o[1] = f * (m2 - m6);             // m02 - m20
            o[2] = f * (m3 - m1);             // m10 - m01
        }
        __syncthreads();         // sout ready; sbuf[buf] fully consumed

        // prefetch tile t + STAGES*stride into the buffer just freed
        // (issued BEFORE the store so loads hit DRAM earlier)
        long long nt = (long long)t + (long long)STAGES * stride;
        if (nt < ntiles) {
            const float4* gp = in + (size_t)nt * T_INF4;
            float4* sp = reinterpret_cast<float4*>(sbuf[buf]);
#pragma unroll
            for (int i = tid; i < T_INF4; i += THREADS)
                cp_async16(&sp[i], &gp[i]);
        }
        cp_commit();             // exactly one group per iteration

        // coalesced float4 streaming store of this tile's output
        float4* op = out + (size_t)t * T_OUTF4;
        const float4* so4 = reinterpret_cast<const float4*>(sout);
#pragma unroll
        for (int i = tid; i < T_OUTF4; i += THREADS)
            __stcs(&op[i], so4[i]);

        buf = (buf == STAGES - 1) ? 0 : buf + 1;
    }
    cp_wait<0>();                // drain before exit
}

// Scalar tail for n % TILE != 0 (not hit for B=4194304, kept for safety).
__global__ void mat2twist_tail_kernel(const float* __restrict__ in,
                                      float* __restrict__ out,
                                      int start, int n) {
    int i = start + blockIdx.x * blockDim.x + threadIdx.x;
    if (i >= n) return;
    const float* a = in + (size_t)i * 9;
    float f = twist_factor(a[0] + a[4] + a[8]);
    float* o = out + (size_t)i * 3;
    o[0] = f * (a[7] - a[5]);
    o[1] = f * (a[2] - a[6]);
    o[2] = f * (a[3] - a[1]);
}

extern "C" void kernel_launch(void* const* d_in, const int* in_sizes, int n_in,
                              void* d_out, int out_size) {
    const float* in = (const float*)d_in[0];
    float* out = (float*)d_out;
    int n = in_sizes[0] / 9;        // number of 3x3 matrices
    int ntiles = n / TILE;          // full tiles (B=4194304 -> 16384)
    int done = ntiles * TILE;
    int rem = n - done;

    if (ntiles > 0) {
        // grid chosen so ntiles % grid == 0 when possible -> perfect balance.
        // 1024 blocks: all resident (7/SM x 152 = 1064), 16 tiles each.
        int grid = 1024;
        if (grid > ntiles) grid = ntiles;
        while (grid > 1 && (ntiles % grid) != 0) grid--;   // keep balance
        mat2twist_pipe3_kernel<<<grid, THREADS>>>(
            (const float4*)in, (float4*)out, ntiles);
    }
    if (rem > 0) {
        int tthreads = 256;
        int tblocks = (rem + tthreads - 1) / tthreads;
        mat2twist_tail_kernel<<<tblocks, tthreads>>>(in, out, done, n);
    }
}

// round 16
// speedup vs baseline: 1.0434x; 1.0434x over previous
#include <cuda_runtime.h>
#include <cuda_bf16.h>

// Mat2Twist: out[b] = theta * axis, theta = acos((tr-1)/2),
// axis = (m21-m12, m02-m20, m10-m01) / (2*sin(theta)).
// Uses sin(acos(c)) == sqrt(1-c^2), exact on theta in (0, pi).
//
// R16: 4-stage cp.async ring with distance-2 refill -> ONE block barrier
// per iteration, legally:
//   - iteration i: prefetch tile i+2 into sbuf[(i+2)%4] (a buffer last READ
//     at iteration i-2; the i-1 barrier separates those reads from this
//     write for ALL thread pairs), commit, wait_group<2>, __syncthreads
//     (cross-thread cp.async visibility), compute tile i, store.
//   - output written directly from registers (96 contiguous floats per
//     warp; 3 dense STG.32 per thread) -- no smem staging, no 2nd barrier.
// Smem = 4 x 9KB = 36KB -> 6 blocks/SM, grid = 152*6 = 912.

__device__ __forceinline__ float twist_factor(float tr) {
    float c = 0.5f * (tr - 1.0f);
    c = fminf(fmaxf(c, -1.0f), 1.0f);
    float ang = acosf(c);
    float s2  = fmaxf(fmaf(-c, c, 1.0f), 1e-20f);  // 1 - c^2
    return 0.5f * ang * rsqrtf(s2);                // theta / (2 sin theta)
}

constexpr int THREADS = 256;
constexpr int TILE    = 256;            // matrices per tile (1 per thread)
constexpr int T_INF4  = TILE * 9 / 4;   // 576 float4 in per tile
constexpr int STAGES  = 4;

__device__ __forceinline__ void cp_async16(void* smem_ptr, const void* gptr) {
    unsigned s = (unsigned)__cvta_generic_to_shared(smem_ptr);
    asm volatile("cp.async.cg.shared.global [%0], [%1], 16;\n"
                 :: "r"(s), "l"(gptr));
}
__device__ __forceinline__ void cp_commit() {
    asm volatile("cp.async.commit_group;\n" ::: "memory");
}
template <int N>
__device__ __forceinline__ void cp_wait() {
    asm volatile("cp.async.wait_group %0;\n" :: "n"(N) : "memory");
}

__global__ __launch_bounds__(THREADS)
void mat2twist_pipe4_kernel(const float4* __restrict__ in,
                            float* __restrict__ out, int ntiles) {
    __shared__ float sbuf[STAGES][TILE * 9];  // 4 x 9KB input ring
    const int tid = threadIdx.x;

    const int t0     = blockIdx.x;
    const int stride = gridDim.x;

    // prologue: prefetch tiles t0, t0+stride into sbuf[0], sbuf[1]
#pragma unroll
    for (int p = 0; p < 2; ++p) {
        long long tile = (long long)t0 + (long long)p * stride;
        if (tile < ntiles) {
            const float4* gp = in + (size_t)tile * T_INF4;
            float4* sp = reinterpret_cast<float4*>(sbuf[p]);
#pragma unroll
            for (int i = tid; i < T_INF4; i += THREADS)
                cp_async16(&sp[i], &gp[i]);
        }
        cp_commit();
    }

    int it = 0;  // iteration counter -> ring index
    for (int t = t0; t < ntiles; t += stride, ++it) {
        // prefetch tile t+2*stride into sbuf[(it+2)%4].
        // That buffer was last read at iteration it-2; the barrier at
        // iteration it-1 (below, executed by all threads between their
        // it-2 compute and this point) makes this write safe.
        long long nt = (long long)t + 2LL * stride;
        int pbuf = (it + 2) & (STAGES - 1);
        if (nt < ntiles) {
            const float4* gp = in + (size_t)nt * T_INF4;
            float4* sp = reinterpret_cast<float4*>(sbuf[pbuf]);
#pragma unroll
            for (int i = tid; i < T_INF4; i += THREADS)
                cp_async16(&sp[i], &gp[i]);
        }
        cp_commit();             // exactly one group per iteration

        cp_wait<2>();            // own copies for tile t complete
        __syncthreads();         // cross-thread visibility of tile t

        // compute: one matrix per thread (stride-9 LDS base: conflict-free),
        // store 3 floats straight to global (dense 384B span per warp)
        const float* a = sbuf[it & (STAGES - 1)] + 9 * tid;
        float m1 = a[1], m2 = a[2], m3 = a[3];
        float m5 = a[5], m6 = a[6], m7 = a[7];
        float f  = twist_factor(a[0] + a[4] + a[8]);
        float* o = out + 3 * ((size_t)t * TILE + tid);
        o[0] = f * (m7 - m5);    // m21 - m12
        o[1] = f * (m2 - m6);    // m02 - m20
        o[2] = f * (m3 - m1);    // m10 - m01
    }
    cp_wait<0>();                // drain before exit
}

// Scalar tail for n % TILE != 0 (not hit for B=4194304, kept for safety).
__global__ void mat2twist_tail_kernel(const float* __restrict__ in,
                                      float* __restrict__ out,
                                      int start, int n) {
    int i = start + blockIdx.x * blockDim.x + threadIdx.x;
    if (i >= n) return;
    const float* a = in + (size_t)i * 9;
    float f = twist_factor(a[0] + a[4] + a[8]);
    float* o = out + (size_t)i * 3;
    o[0] = f * (a[7] - a[5]);
    o[1] = f * (a[2] - a[6]);
    o[2] = f * (a[3] - a[1]);
}

extern "C" void kernel_launch(void* const* d_in, const int* in_sizes, int n_in,
                              void* d_out, int out_size) {
    const float* in = (const float*)d_in[0];
    float* out = (float*)d_out;
    int n = in_sizes[0] / 9;        // number of 3x3 matrices
    int ntiles = n / TILE;          // full tiles (B=4194304 -> 16384)
    int done = ntiles * TILE;
    int rem = n - done;

    if (ntiles > 0) {
        // 152 SMs x 6 blocks/SM (36KB smem/block)
        int grid = 152 * 6;
        if (grid > ntiles) grid = ntiles;
        mat2twist_pipe4_kernel<<<grid, THREADS>>>(
            (const float4*)in, out, ntiles);
    }
    if (rem > 0) {
        int tthreads = 256;
        int tblocks = (rem + tthreads - 1) / tthreads;
        mat2twist_tail_kernel<<<tblocks, tthreads>>>(in, out, done, n);
    }
}

// round 17
// speedup vs baseline: 1.0453x; 1.0018x over previous
#include <cuda_runtime.h>
#include <cuda_bf16.h>

// Mat2Twist: out[b] = theta * axis, theta = acos((tr-1)/2),
// axis = (m21-m12, m02-m20, m10-m01) / (2*sin(theta)).
// Uses sin(acos(c)) == sqrt(1-c^2), exact on theta in (0, pi).
//
// R17: R12's proven 3-stage cp.async ring + two-barrier loop, with the
// output smem staging removed (direct register->global stores).
//   smem: 3 x 9KB = 27KB -> 8 blocks/SM (vs R12's 7), 100% occupancy.
//   The second __syncthreads (after compute) is what makes refilling the
//   just-freed ring buffer legal (separates ALL threads' reads from the
//   refill cp.async writes) -- do not remove it (R15's bug).

__device__ __forceinline__ float twist_factor(float tr) {
    float c = 0.5f * (tr - 1.0f);
    c = fminf(fmaxf(c, -1.0f), 1.0f);
    float ang = acosf(c);
    float s2  = fmaxf(fmaf(-c, c, 1.0f), 1e-20f);  // 1 - c^2
    return 0.5f * ang * rsqrtf(s2);                // theta / (2 sin theta)
}

constexpr int THREADS = 256;
constexpr int TILE    = 256;            // matrices per tile (1 per thread)
constexpr int T_INF4  = TILE * 9 / 4;   // 576 float4 in per tile
constexpr int STAGES  = 3;

__device__ __forceinline__ void cp_async16(void* smem_ptr, const void* gptr) {
    unsigned s = (unsigned)__cvta_generic_to_shared(smem_ptr);
    asm volatile("cp.async.cg.shared.global [%0], [%1], 16;\n"
                 :: "r"(s), "l"(gptr));
}
__device__ __forceinline__ void cp_commit() {
    asm volatile("cp.async.commit_group;\n" ::: "memory");
}
template <int N>
__device__ __forceinline__ void cp_wait() {
    asm volatile("cp.async.wait_group %0;\n" :: "n"(N) : "memory");
}

__global__ __launch_bounds__(THREADS)
void mat2twist_pipe3r_kernel(const float4* __restrict__ in,
                             float* __restrict__ out, int ntiles) {
    __shared__ float sbuf[STAGES][TILE * 9];  // 3 x 9KB input ring
    const int tid = threadIdx.x;

    const int t0     = blockIdx.x;
    const int stride = gridDim.x;

    // prologue: prefetch first STAGES tiles (empty groups keep FIFO exact)
#pragma unroll
    for (int p = 0; p < STAGES; ++p) {
        long long tile = (long long)t0 + (long long)p * stride;
        if (tile < ntiles) {
            const float4* gp = in + (size_t)tile * T_INF4;
            float4* sp = reinterpret_cast<float4*>(sbuf[p]);
#pragma unroll
            for (int i = tid; i < T_INF4; i += THREADS)
                cp_async16(&sp[i], &gp[i]);
        }
        cp_commit();
    }

    int buf = 0;
    for (int t = t0; t < ntiles; t += stride) {
        cp_wait<STAGES - 1>();   // oldest in-flight group (= this buf) done
        __syncthreads();         // cross-thread visibility of tile t

        // compute: one matrix per thread (stride-9 LDS base: conflict-free);
        // results stored directly to global (dense 384B span per warp per
        // store instruction).
        const float* a = sbuf[buf] + 9 * tid;
        float m1 = a[1], m2 = a[2], m3 = a[3];
        float m5 = a[5], m6 = a[6], m7 = a[7];
        float f  = twist_factor(a[0] + a[4] + a[8]);
        float* o = out + 3 * ((size_t)t * TILE + tid);
        float r0 = f * (m7 - m5);    // m21 - m12
        float r1 = f * (m2 - m6);    // m02 - m20
        float r2 = f * (m3 - m1);    // m10 - m01

        __syncthreads();         // ALL threads done reading sbuf[buf]
                                 // -> refill below is race-free (R15 lesson)

        // prefetch tile t + STAGES*stride into the buffer just freed
        long long nt = (long long)t + (long long)STAGES * stride;
        if (nt < ntiles) {
            const float4* gp = in + (size_t)nt * T_INF4;
            float4* sp = reinterpret_cast<float4*>(sbuf[buf]);
#pragma unroll
            for (int i = tid; i < T_INF4; i += THREADS)
                cp_async16(&sp[i], &gp[i]);
        }
        cp_commit();             // exactly one group per iteration

        // stores issued after the prefetch so loads hit DRAM first
        o[0] = r0;
        o[1] = r1;
        o[2] = r2;

        buf = (buf == STAGES - 1) ? 0 : buf + 1;
    }
    cp_wait<0>();                // drain before exit
}

// Scalar tail for n % TILE != 0 (not hit for B=4194304, kept for safety).
__global__ void mat2twist_tail_kernel(const float* __restrict__ in,
                                      float* __restrict__ out,
                                      int start, int n) {
    int i = start + blockIdx.x * blockDim.x + threadIdx.x;
    if (i >= n) return;
    const float* a = in + (size_t)i * 9;
    float f = twist_factor(a[0] + a[4] + a[8]);
    float* o = out + (size_t)i * 3;
    o[0] = f * (a[7] - a[5]);
    o[1] = f * (a[2] - a[6]);
    o[2] = f * (a[3] - a[1]);
}

extern "C" void kernel_launch(void* const* d_in, const int* in_sizes, int n_in,
                              void* d_out, int out_size) {
    const float* in = (const float*)d_in[0];
    float* out = (float*)d_out;
    int n = in_sizes[0] / 9;        // number of 3x3 matrices
    int ntiles = n / TILE;          // full tiles (B=4194304 -> 16384)
    int done = ntiles * TILE;
    int rem = n - done;

    if (ntiles > 0) {
        // 152 SMs x 8 blocks/SM (27KB smem/block) -> full occupancy
        int grid = 152 * 8;
        if (grid > ntiles) grid = ntiles;
        mat2twist_pipe3r_kernel<<<grid, THREADS>>>(
            (const float4*)in, out, ntiles);
    }
    if (rem > 0) {
        int tthreads = 256;
        int tblocks = (rem + tthreads - 1) / tthreads;
        mat2twist_tail_kernel<<<tblocks, tthreads>>>(in, out, done, n);
    }
}